// round 9
// baseline (speedup 1.0000x reference)
#include <cuda_runtime.h>
#include <cuda_bf16.h>
#include <math.h>

#define BB 1024
#define TT 256
#define CC 384
#define HH 64

// Scratch for projected q, k, v: 3 x 64 MiB (device globals — allowed, no allocs)
__device__ float g_q[BB * TT * HH];
__device__ float g_k[BB * TT * HH];
__device__ float g_v[BB * TT * HH];

// ---------------------------------------------------------------------------
// Projection: [262144, 384] x ([384,64] x3 fused as N=192) -> g_q, g_k, g_v
// BM=64, BN=192 (full), BK=32. 256 threads, 4x12 micro-tile per thread.
// ---------------------------------------------------------------------------
__global__ __launch_bounds__(256) void proj_kernel(
    const float* __restrict__ x,
    const float* __restrict__ Wk,
    const float* __restrict__ Wq,
    const float* __restrict__ Wv)
{
    __shared__ float xs[32][68];    // [k][m], transposed, padded (272B rows, 16B aligned)
    __shared__ float ws[32][196];   // [k][n], n: 0-63 q | 64-127 k | 128-191 v

    const int tid = threadIdx.x;
    const int m0  = blockIdx.x * 64;
    const int tx  = tid & 15;   // n-group (cols jj*16+tx)
    const int ty  = tid >> 4;   // m-group (rows ty*4+i)

    float acc[4][12];
#pragma unroll
    for (int i = 0; i < 4; ++i)
#pragma unroll
        for (int j = 0; j < 12; ++j) acc[i][j] = 0.0f;

    for (int k0 = 0; k0 < CC; k0 += 32) {
        // --- load x tile 64x32, store transposed ---
        {
            const int c4 = tid & 7;   // float4 index within 32-col row
            const int r  = tid >> 3;  // 0..31
#pragma unroll
            for (int h = 0; h < 2; ++h) {
                const int row = r + h * 32;
                float4 v4 = *(const float4*)&x[(size_t)(m0 + row) * CC + k0 + c4 * 4];
                xs[c4 * 4 + 0][row] = v4.x;
                xs[c4 * 4 + 1][row] = v4.y;
                xs[c4 * 4 + 2][row] = v4.z;
                xs[c4 * 4 + 3][row] = v4.w;
            }
        }
        // --- load W tiles: q, k, v each 32x64 ---
        {
            const int c4 = tid & 15;  // 0..15 float4 cols
            const int r  = tid >> 4;  // 0..15
#pragma unroll
            for (int h = 0; h < 2; ++h) {
                const int row = r + h * 16;
                float4 aq = *(const float4*)&Wq[(size_t)(k0 + row) * HH + c4 * 4];
                float4 ak = *(const float4*)&Wk[(size_t)(k0 + row) * HH + c4 * 4];
                float4 av = *(const float4*)&Wv[(size_t)(k0 + row) * HH + c4 * 4];
                *(float4*)&ws[row][  0 + c4 * 4] = aq;
                *(float4*)&ws[row][ 64 + c4 * 4] = ak;
                *(float4*)&ws[row][128 + c4 * 4] = av;
            }
        }
        __syncthreads();

#pragma unroll
        for (int kk = 0; kk < 32; ++kk) {
            float4 xf4 = *(const float4*)&xs[kk][ty * 4];
            float xf[4] = {xf4.x, xf4.y, xf4.z, xf4.w};
            float wf[12];
#pragma unroll
            for (int jj = 0; jj < 12; ++jj) wf[jj] = ws[kk][jj * 16 + tx];
#pragma unroll
            for (int i = 0; i < 4; ++i)
#pragma unroll
                for (int jj = 0; jj < 12; ++jj)
                    acc[i][jj] = fmaf(xf[i], wf[jj], acc[i][jj]);
        }
        __syncthreads();
    }

    // write out to q/k/v scratch
#pragma unroll
    for (int jj = 0; jj < 12; ++jj) {
        const int col = jj * 16 + tx;           // 0..191
        const int mat = col >> 6;               // 0:q 1:k 2:v
        const int hh  = col & 63;
        float* dst = (mat == 0) ? g_q : (mat == 1) ? g_k : g_v;
#pragma unroll
        for (int i = 0; i < 4; ++i)
            dst[(size_t)(m0 + ty * 4 + i) * HH + hh] = acc[i][jj];
    }
}

// ---------------------------------------------------------------------------
// Attention: one CTA per batch. K,V (256x64 fp32 each) resident in SMEM.
// Thread t owns query row t; online-softmax flash accumulation in registers.
// ---------------------------------------------------------------------------
__global__ __launch_bounds__(256) void attn_kernel(float* __restrict__ out)
{
    extern __shared__ float sm[];
    float* Ks = sm;                 // [256][64]
    float* Vs = sm + TT * HH;       // [256][64]

    const int b   = blockIdx.x;
    const int tid = threadIdx.x;
    const size_t base = (size_t)b * TT * HH;

    // cooperative load of K and V (fully coalesced float4)
    {
        const float4* kg = (const float4*)(g_k + base);
        const float4* vg = (const float4*)(g_v + base);
        float4* ks4 = (float4*)Ks;
        float4* vs4 = (float4*)Vs;
#pragma unroll
        for (int i = 0; i < 16; ++i) {
            ks4[tid + i * 256] = kg[tid + i * 256];
            vs4[tid + i * 256] = vg[tid + i * 256];
        }
    }
    __syncthreads();

    // load this thread's query row into registers
    float qv[64];
    {
        const float4* qg = (const float4*)(g_q + base + (size_t)tid * HH);
#pragma unroll
        for (int i = 0; i < 16; ++i) {
            float4 t4 = qg[i];
            qv[4 * i + 0] = t4.x; qv[4 * i + 1] = t4.y;
            qv[4 * i + 2] = t4.z; qv[4 * i + 3] = t4.w;
        }
    }

    float acc[64];
#pragma unroll
    for (int d = 0; d < 64; ++d) acc[d] = 0.0f;

    float m = -INFINITY;
    float l = 0.0f;
    const float scale = 0.05103103630798287f;  // 384^-0.5 (scale uses embed dim C)

    for (int j = 0; j <= tid; ++j) {
        // score = q . K[j]
        const float4* krow = (const float4*)(Ks + j * HH);
        float s0 = 0.f, s1 = 0.f, s2 = 0.f, s3 = 0.f;
#pragma unroll
        for (int i = 0; i < 16; ++i) {
            float4 k4 = krow[i];
            s0 = fmaf(qv[4 * i + 0], k4.x, s0);
            s1 = fmaf(qv[4 * i + 1], k4.y, s1);
            s2 = fmaf(qv[4 * i + 2], k4.z, s2);
            s3 = fmaf(qv[4 * i + 3], k4.w, s3);
        }
        float s = ((s0 + s1) + (s2 + s3)) * scale;

        // online softmax update
        if (s > m) {
            float corr = __expf(m - s);   // first iter: exp(-inf) = 0
            l *= corr;
#pragma unroll
            for (int d = 0; d < 64; ++d) acc[d] *= corr;
            m = s;
        }
        float p = __expf(s - m);
        l += p;

        const float4* vrow = (const float4*)(Vs + j * HH);
#pragma unroll
        for (int i = 0; i < 16; ++i) {
            float4 v4 = vrow[i];
            acc[4 * i + 0] = fmaf(p, v4.x, acc[4 * i + 0]);
            acc[4 * i + 1] = fmaf(p, v4.y, acc[4 * i + 1]);
            acc[4 * i + 2] = fmaf(p, v4.z, acc[4 * i + 2]);
            acc[4 * i + 3] = fmaf(p, v4.w, acc[4 * i + 3]);
        }
    }

    const float inv = 1.0f / l;
    float4* og = (float4*)(out + base + (size_t)tid * HH);
#pragma unroll
    for (int i = 0; i < 16; ++i) {
        og[i] = make_float4(acc[4 * i + 0] * inv, acc[4 * i + 1] * inv,
                            acc[4 * i + 2] * inv, acc[4 * i + 3] * inv);
    }
}

extern "C" void kernel_launch(void* const* d_in, const int* in_sizes, int n_in,
                              void* d_out, int out_size)
{
    (void)in_sizes; (void)n_in; (void)out_size;
    const float* x  = (const float*)d_in[0];
    const float* Wk = (const float*)d_in[1];
    const float* Wq = (const float*)d_in[2];
    const float* Wv = (const float*)d_in[3];
    float* out = (float*)d_out;

    proj_kernel<<<(BB * TT) / 64, 256>>>(x, Wk, Wq, Wv);

    cudaFuncSetAttribute(attn_kernel, cudaFuncAttributeMaxDynamicSharedMemorySize,
                         2 * TT * HH * (int)sizeof(float));
    attn_kernel<<<BB, 256, 2 * TT * HH * sizeof(float)>>>(out);
}

// round 11
// speedup vs baseline: 1.5338x; 1.5338x over previous
#include <cuda_runtime.h>
#include <cuda_bf16.h>
#include <math.h>
#include <stdint.h>

#define BB 1024
#define TT 256
#define CC 384
#define HH 64

// ---------------------------------------------------------------------------
// Device scratch (no allocations allowed)
// ---------------------------------------------------------------------------
__device__ float g_q[BB * TT * HH];
__device__ float g_k[BB * TT * HH];
__device__ float g_v[BB * TT * HH];
// Pre-swizzled SMEM image of W^T bf16 hi/lo per 64-wide K chunk:
// [6 chunks][hi 24576 B | lo 24576 B]; within each: [k 0..63][n-chunk 0..23]
// 16B chunks, chunk index swizzled: c' = (c & ~7) | ((c ^ k) & 7)
__device__ unsigned char g_wb[6 * 2 * 24576];

// ---------------------------------------------------------------------------
// helpers
// ---------------------------------------------------------------------------
__device__ __forceinline__ uint32_t smem_u32(const void* p) {
    uint32_t a;
    asm("{ .reg .u64 t; cvta.to.shared.u64 t, %1; cvt.u32.u64 %0, t; }"
        : "=r"(a) : "l"(p));
    return a;
}

__device__ __forceinline__ void ldsm_x4(uint32_t r[4], uint32_t addr) {
    asm volatile("ldmatrix.sync.aligned.m8n8.x4.shared.b16 {%0,%1,%2,%3}, [%4];"
                 : "=r"(r[0]), "=r"(r[1]), "=r"(r[2]), "=r"(r[3]) : "r"(addr));
}

__device__ __forceinline__ void ldsm_x4_trans(uint32_t r[4], uint32_t addr) {
    asm volatile("ldmatrix.sync.aligned.m8n8.x4.trans.shared.b16 {%0,%1,%2,%3}, [%4];"
                 : "=r"(r[0]), "=r"(r[1]), "=r"(r[2]), "=r"(r[3]) : "r"(addr));
}

__device__ __forceinline__ void mma_bf16(float c[4], const uint32_t a[4],
                                         const uint32_t b[2]) {
    asm volatile(
        "mma.sync.aligned.m16n8k16.row.col.f32.bf16.bf16.f32 "
        "{%0,%1,%2,%3}, {%4,%5,%6,%7}, {%8,%9}, {%0,%1,%2,%3};"
        : "+f"(c[0]), "+f"(c[1]), "+f"(c[2]), "+f"(c[3])
        : "r"(a[0]), "r"(a[1]), "r"(a[2]), "r"(a[3]), "r"(b[0]), "r"(b[1]));
}

__device__ __forceinline__ uint32_t pack_bf16(float a, float b) {
    __nv_bfloat162 t = __floats2bfloat162_rn(a, b);
    return *reinterpret_cast<uint32_t*>(&t);
}

// ---------------------------------------------------------------------------
// Setup: build the pre-swizzled W^T bf16 hi/lo image.
// n = mat*64 + h (mat 0:q, 1:k, 2:v). 6*64*192 = 73728 elements.
// ---------------------------------------------------------------------------
__global__ void setup_wb_kernel(const float* __restrict__ Wk,
                                const float* __restrict__ Wq,
                                const float* __restrict__ Wv)
{
    int idx = blockIdx.x * 256 + threadIdx.x;
    if (idx >= 6 * 64 * 192) return;
    int ck  = idx / (64 * 192);
    int rem = idx % (64 * 192);
    int k   = rem / 192;
    int n   = rem % 192;
    int mat = n >> 6, h = n & 63;
    const float* W = (mat == 0) ? Wq : (mat == 1) ? Wk : Wv;
    float v = W[(size_t)(ck * 64 + k) * HH + h];
    __nv_bfloat16 hi = __float2bfloat16(v);
    __nv_bfloat16 lo = __float2bfloat16(v - __bfloat162float(hi));
    int c  = n >> 3;
    int cs = (c & ~7) | ((c ^ k) & 7);
    uint32_t off = (uint32_t)k * 384u + (uint32_t)cs * 16u + (uint32_t)(n & 7) * 2u;
    unsigned char* base = g_wb + (size_t)ck * 49152;
    *reinterpret_cast<__nv_bfloat16*>(base + off)         = hi;
    *reinterpret_cast<__nv_bfloat16*>(base + 24576 + off) = lo;
}

// ---------------------------------------------------------------------------
// QKV projection via mma.sync bf16 split (3 passes, fp32 accumulate).
// CTA: M=128, N=192, K=384 in 6 chunks of 64. 256 threads = 8 warps (4m x 2n).
// Warp tile: 32m x 96n -> acc[2][12][4].
// ---------------------------------------------------------------------------
#define SM_A_HI  0
#define SM_A_LO  16384
#define SM_B_HI  32768
#define SM_B_LO  57344
#define SM_TOTAL 81920

__global__ __launch_bounds__(256) void qkv_mma_kernel(const float* __restrict__ x)
{
    extern __shared__ char smem[];
    const uint32_t sb = smem_u32(smem);
    const int tid  = threadIdx.x;
    const int wid  = tid >> 5;
    const int lane = tid & 31;
    const int m0   = blockIdx.x * 128;
    const int wm   = wid & 3;    // m offset 32*wm
    const int wn   = wid >> 2;   // n offset 96*wn

    float acc[2][12][4];
#pragma unroll
    for (int i = 0; i < 2; ++i)
#pragma unroll
        for (int j = 0; j < 12; ++j)
#pragma unroll
            for (int r = 0; r < 4; ++r) acc[i][j][r] = 0.0f;

    // A staging assignment: thread handles row r8 = tid>>1, k-half hf = tid&1
    const int r8 = tid >> 1;
    const int hf = tid & 1;
    const float* xrow = x + (size_t)(m0 + r8) * CC + hf * 32;

    // precomputed ldmatrix smem addresses (invariant over chunks except kk)
    // A: row = wm*32 + t16*16 + (lane&15), c8 = kk*2 + (lane>>4), swizzle c8^(row&7)
    const int a_row0 = wm * 32 + (lane & 15);
    const int a_chi  = lane >> 4;
    // B: k = kk*16 + (lane&15), c = (wn*96 + nt*16)>>3 + (lane>>4)
    const int b_k0   = lane & 15;

    for (int ck = 0; ck < 6; ++ck) {
        // --- stage A: load x chunk, convert to bf16 hi/lo, store swizzled ---
        {
            const float4* p = (const float4*)(xrow + ck * 64);
#pragma unroll
            for (int jj = 0; jj < 4; ++jj) {
                float4 u = p[2 * jj];
                float4 w = p[2 * jj + 1];
                float f0 = u.x, f1 = u.y, f2 = u.z, f3 = u.w;
                float f4 = w.x, f5 = w.y, f6 = w.z, f7 = w.w;
                float h0 = __bfloat162float(__float2bfloat16(f0));
                float h1 = __bfloat162float(__float2bfloat16(f1));
                float h2 = __bfloat162float(__float2bfloat16(f2));
                float h3 = __bfloat162float(__float2bfloat16(f3));
                float h4 = __bfloat162float(__float2bfloat16(f4));
                float h5 = __bfloat162float(__float2bfloat16(f5));
                float h6 = __bfloat162float(__float2bfloat16(f6));
                float h7 = __bfloat162float(__float2bfloat16(f7));
                uint4 hv, lv;
                hv.x = pack_bf16(h0, h1); hv.y = pack_bf16(h2, h3);
                hv.z = pack_bf16(h4, h5); hv.w = pack_bf16(h6, h7);
                lv.x = pack_bf16(f0 - h0, f1 - h1); lv.y = pack_bf16(f2 - h2, f3 - h3);
                lv.z = pack_bf16(f4 - h4, f5 - h5); lv.w = pack_bf16(f6 - h6, f7 - h7);
                int c8 = hf * 4 + jj;
                uint32_t off = (uint32_t)r8 * 128u + (uint32_t)((c8 ^ (r8 & 7)) * 16);
                *reinterpret_cast<uint4*>(smem + SM_A_HI + off) = hv;
                *reinterpret_cast<uint4*>(smem + SM_A_LO + off) = lv;
            }
        }
        // --- stage B: copy pre-swizzled image (hi+lo = 48 KB) ---
        {
            const uint4* src = reinterpret_cast<const uint4*>(g_wb + (size_t)ck * 49152);
            uint4* dst = reinterpret_cast<uint4*>(smem + SM_B_HI);
#pragma unroll
            for (int i = 0; i < 12; ++i) dst[tid + i * 256] = src[tid + i * 256];
        }
        __syncthreads();

        // --- compute: 4 k16 steps ---
#pragma unroll 1
        for (int kk = 0; kk < 4; ++kk) {
            uint32_t ah[2][4], al[2][4];
#pragma unroll
            for (int t16 = 0; t16 < 2; ++t16) {
                int row = a_row0 + t16 * 16;
                int c8  = kk * 2 + a_chi;
                uint32_t off = (uint32_t)row * 128u + (uint32_t)((c8 ^ (row & 7)) * 16);
                ldsm_x4(ah[t16], sb + SM_A_HI + off);
                ldsm_x4(al[t16], sb + SM_A_LO + off);
            }
            uint32_t bh[12][2], bl[12][2];
#pragma unroll
            for (int nt = 0; nt < 6; ++nt) {
                int k = kk * 16 + b_k0;
                int c = ((wn * 96 + nt * 16) >> 3) + (lane >> 4);
                int cs = (c & ~7) | ((c ^ k) & 7);
                uint32_t off = (uint32_t)k * 384u + (uint32_t)cs * 16u;
                uint32_t t[4];
                ldsm_x4_trans(t, sb + SM_B_HI + off);
                bh[2*nt][0] = t[0]; bh[2*nt][1] = t[1];
                bh[2*nt+1][0] = t[2]; bh[2*nt+1][1] = t[3];
                ldsm_x4_trans(t, sb + SM_B_LO + off);
                bl[2*nt][0] = t[0]; bl[2*nt][1] = t[1];
                bl[2*nt+1][0] = t[2]; bl[2*nt+1][1] = t[3];
            }
#pragma unroll
            for (int t16 = 0; t16 < 2; ++t16)
#pragma unroll
                for (int nt8 = 0; nt8 < 12; ++nt8) {
                    mma_bf16(acc[t16][nt8], ah[t16], bh[nt8]);  // hi*hi
                    mma_bf16(acc[t16][nt8], ah[t16], bl[nt8]);  // hi*lo
                    mma_bf16(acc[t16][nt8], al[t16], bh[nt8]);  // lo*hi
                }
        }
        __syncthreads();
    }

    // --- epilogue: write fp32 results to g_q / g_k / g_v ---
#pragma unroll
    for (int t16 = 0; t16 < 2; ++t16) {
        int row0 = m0 + wm * 32 + t16 * 16 + (lane >> 2);
#pragma unroll
        for (int nt8 = 0; nt8 < 12; ++nt8) {
            int col = wn * 96 + nt8 * 8 + (lane & 3) * 2;
            int mat = col >> 6;
            int h   = col & 63;
            float* dst = (mat == 0) ? g_q : (mat == 1) ? g_k : g_v;
            *reinterpret_cast<float2*>(dst + (size_t)row0 * HH + h) =
                make_float2(acc[t16][nt8][0], acc[t16][nt8][1]);
            *reinterpret_cast<float2*>(dst + (size_t)(row0 + 8) * HH + h) =
                make_float2(acc[t16][nt8][2], acc[t16][nt8][3]);
        }
    }
}

// ---------------------------------------------------------------------------
// Attention: one CTA per batch, K/V resident in SMEM, one thread per query row.
// Warp pairs on each SMSP get complementary triangle chunks (sum = 288).
// ---------------------------------------------------------------------------
__global__ __launch_bounds__(256) void attn_kernel(float* __restrict__ out)
{
    extern __shared__ float sm[];
    float* Ks = sm;                 // [256][64]
    float* Vs = sm + TT * HH;       // [256][64]

    const int b    = blockIdx.x;
    const int tid  = threadIdx.x;
    const int wid  = tid >> 5;
    const int lane = tid & 31;
    const size_t base = (size_t)b * TT * HH;

    const int chunk = (wid < 4) ? wid : (11 - wid);
    const int row   = chunk * 32 + lane;

    {
        const float4* kg = (const float4*)(g_k + base);
        const float4* vg = (const float4*)(g_v + base);
        float4* ks4 = (float4*)Ks;
        float4* vs4 = (float4*)Vs;
#pragma unroll
        for (int i = 0; i < 16; ++i) {
            ks4[tid + i * 256] = kg[tid + i * 256];
            vs4[tid + i * 256] = vg[tid + i * 256];
        }
    }
    __syncthreads();

    float qv[64];
    {
        const float4* qg = (const float4*)(g_q + base + (size_t)row * HH);
#pragma unroll
        for (int i = 0; i < 16; ++i) {
            float4 t4 = qg[i];
            qv[4*i+0] = t4.x; qv[4*i+1] = t4.y;
            qv[4*i+2] = t4.z; qv[4*i+3] = t4.w;
        }
    }

    float acc[64];
#pragma unroll
    for (int d = 0; d < 64; ++d) acc[d] = 0.0f;

    float m = -INFINITY;
    float l = 0.0f;
    const float scale = 0.05103103630798287f;  // 384^-0.5 (embed dim C)

    for (int j = 0; j <= row; ++j) {
        const float4* krow = (const float4*)(Ks + j * HH);
        float s0 = 0.f, s1 = 0.f, s2 = 0.f, s3 = 0.f;
#pragma unroll
        for (int i = 0; i < 16; ++i) {
            float4 k4 = krow[i];
            s0 = fmaf(qv[4*i+0], k4.x, s0);
            s1 = fmaf(qv[4*i+1], k4.y, s1);
            s2 = fmaf(qv[4*i+2], k4.z, s2);
            s3 = fmaf(qv[4*i+3], k4.w, s3);
        }
        float s = ((s0 + s1) + (s2 + s3)) * scale;

        if (s > m) {
            float corr = __expf(m - s);
            l *= corr;
#pragma unroll
            for (int d = 0; d < 64; ++d) acc[d] *= corr;
            m = s;
        }
        float p = __expf(s - m);
        l += p;

        const float4* vrow = (const float4*)(Vs + j * HH);
#pragma unroll
        for (int i = 0; i < 16; ++i) {
            float4 v4 = vrow[i];
            acc[4*i+0] = fmaf(p, v4.x, acc[4*i+0]);
            acc[4*i+1] = fmaf(p, v4.y, acc[4*i+1]);
            acc[4*i+2] = fmaf(p, v4.z, acc[4*i+2]);
            acc[4*i+3] = fmaf(p, v4.w, acc[4*i+3]);
        }
    }

    const float inv = 1.0f / l;
    float4* og = (float4*)(out + base + (size_t)row * HH);
#pragma unroll
    for (int i = 0; i < 16; ++i) {
        og[i] = make_float4(acc[4*i+0] * inv, acc[4*i+1] * inv,
                            acc[4*i+2] * inv, acc[4*i+3] * inv);
    }
}

// ---------------------------------------------------------------------------
extern "C" void kernel_launch(void* const* d_in, const int* in_sizes, int n_in,
                              void* d_out, int out_size)
{
    (void)in_sizes; (void)n_in; (void)out_size;
    const float* x  = (const float*)d_in[0];
    const float* Wk = (const float*)d_in[1];
    const float* Wq = (const float*)d_in[2];
    const float* Wv = (const float*)d_in[3];
    float* out = (float*)d_out;

    setup_wb_kernel<<<(6 * 64 * 192 + 255) / 256, 256>>>(Wk, Wq, Wv);

    cudaFuncSetAttribute(qkv_mma_kernel, cudaFuncAttributeMaxDynamicSharedMemorySize,
                         SM_TOTAL);
    qkv_mma_kernel<<<(BB * TT) / 128, 256, SM_TOTAL>>>(x);

    cudaFuncSetAttribute(attn_kernel, cudaFuncAttributeMaxDynamicSharedMemorySize,
                         2 * TT * HH * (int)sizeof(float));
    attn_kernel<<<BB, 256, 2 * TT * HH * sizeof(float)>>>(out);
}